// round 1
// baseline (speedup 1.0000x reference)
#include <cuda_runtime.h>

#define NN 8
#define TT 64
#define VV 200
#define FF 64
#define FOUT 64
#define NT (NN*TT)   // 512
#define TU 40        // u-tile in kernelB (5 exact tiles)
#define VT 32        // v-tile in kernelB (7 tiles, last padded)

// scratch (static device globals are allowed; no allocation at runtime)
__device__ float g_y1[(size_t)NT*VV*FOUT];
__device__ float g_y2[(size_t)NT*VV*FOUT];
__device__ float g_d[(size_t)NT*VV];

// ---------------------------------------------------------------------------
// kernelD: d[nt,v] = sum_u min(S[nt,u,v], S[nt,v,u])
// ---------------------------------------------------------------------------
__global__ void kernelD(const float* __restrict__ S) {
    int nt = blockIdx.x;
    int v  = threadIdx.x;
    if (v >= VV) return;
    const float* Snt = S + (size_t)nt * VV * VV;
    float s = 0.f;
    for (int u = 0; u < VV; ++u) {
        float a = Snt[(size_t)v * VV + u];   // row (contiguous per thread)
        float b = Snt[(size_t)u * VV + v];   // column (coalesced across threads)
        s += fminf(a, b);
    }
    g_d[(size_t)nt * VV + v] = s;
}

// ---------------------------------------------------------------------------
// kernelA: y1 = x@Theta1, y2 = x@Theta2, base = Att[v,v]*(x@Theta0) -> out
// grid (7, NT), 256 threads. Each block: one 32-row u-tile of one (n,t).
// smem: Theta[3*64*64] (48KB) + xs[32*64] (8KB)
// ---------------------------------------------------------------------------
__global__ void kernelA(const float* __restrict__ x,
                        const float* __restrict__ Att,
                        const float* __restrict__ Theta,
                        float* __restrict__ out_base) {
    extern __shared__ float sA[];
    float* Th = sA;                 // 3*64*64 = 12288 floats
    float* xs = sA + 3 * 64 * 64;   // 32*64   = 2048 floats

    int it  = blockIdx.x;           // u-tile 0..6
    int nt  = blockIdx.y;
    int n   = nt / TT;
    int tid = threadIdx.x;          // 256

    for (int i = tid; i < 3 * 64 * 64; i += 256) Th[i] = Theta[i];

    const float* xnt = x + (size_t)nt * VV * FF;
    int ubase = it * 32;
    for (int i = tid; i < 32 * 64; i += 256) {
        int r = i >> 6, c = i & 63;
        int u = ubase + r;
        xs[i] = (u < VV) ? xnt[(size_t)u * FF + c] : 0.f;
    }
    __syncthreads();

    int uo  = tid >> 3;             // 0..31 : local u row
    int fo8 = tid & 7;              // 0..7  : fo block of 8
    int u = ubase + uo;
    if (u >= VV) return;

    float a0[8], a1[8], a2[8];
#pragma unroll
    for (int j = 0; j < 8; ++j) { a0[j] = 0.f; a1[j] = 0.f; a2[j] = 0.f; }

    const float* xr = xs + uo * 64;
#pragma unroll 8
    for (int f = 0; f < 64; ++f) {
        float xv = xr[f];
        const float* t0 = Th + (0 * 64 + f) * 64 + fo8 * 8;
        const float* t1 = Th + (1 * 64 + f) * 64 + fo8 * 8;
        const float* t2 = Th + (2 * 64 + f) * 64 + fo8 * 8;
#pragma unroll
        for (int j = 0; j < 8; ++j) {
            a0[j] += xv * t0[j];
            a1[j] += xv * t1[j];
            a2[j] += xv * t2[j];
        }
    }

    float attvv = Att[((size_t)n * VV + u) * VV + u];
    size_t ob = ((size_t)nt * VV + u) * FOUT + fo8 * 8;
#pragma unroll
    for (int j = 0; j < 8; ++j) {
        out_base[ob + j] = attvv * a0[j];   // k=0 (diagonal) term, pre-relu
        g_y1[ob + j] = a1[j];
        g_y2[ob + j] = a2[j];
    }
}

// ---------------------------------------------------------------------------
// kernelB: out[nt,v,fo] = relu( base + sum_u c1[u,v]*y1[u,fo] + c2[u,v]*y2[u,fo] )
//   c1 = l*Att[u,v],  c2 = (2*l*l - (u==v))*Att[u,v]
//   l  = (u==v ? d[u]-1 : 0) - min(S[u,v], S[v,u])
// grid (7, NT), 128 threads. Per-thread tile 4v x 4fo.
// smem: St[32][201] + cs1[40][32] + cs2[40][32] + ys1[40][64] + ys2[40][64]
// ---------------------------------------------------------------------------
__global__ void kernelB(const float* __restrict__ Att,
                        const float* __restrict__ S,
                        float* __restrict__ out) {
    extern __shared__ float sB[];
    float* St  = sB;                 // 32*201 = 6432 (padded rows: conflict-free cols)
    float* cs1 = St  + 32 * 201;     // 40*32
    float* cs2 = cs1 + TU * VT;
    float* ys1 = cs2 + TU * VT;      // 40*64
    float* ys2 = ys1 + TU * 64;

    int vt = blockIdx.x;             // 0..6
    int nt = blockIdx.y;
    int n  = nt / TT;
    int v0 = vt * VT;
    int tid = threadIdx.x;           // 128

    const float* Snt = S   + (size_t)nt * VV * VV;
    const float* Atn = Att + (size_t)n  * VV * VV;

    // Stage S rows [v0, v0+32) (all 200 cols) -> coalesced; reused every u-tile.
    for (int i = tid; i < VT * VV; i += 128) {
        int r = i / VV, c = i % VV;
        int v = v0 + r;
        St[r * 201 + c] = (v < VV) ? Snt[(size_t)v * VV + c] : 0.f;
    }

    int vr = tid >> 4;               // 0..7  -> v = v0 + 4*vr + i
    int fq = tid & 15;               // 0..15 -> fo = 4*fq + j
    float acc[4][4];
#pragma unroll
    for (int i = 0; i < 4; ++i) {
        int v = v0 + vr * 4 + i;
        if (v < VV) {
            const float* op = out + ((size_t)nt * VV + v) * FOUT + fq * 4;
#pragma unroll
            for (int j = 0; j < 4; ++j) acc[i][j] = op[j];
        } else {
#pragma unroll
            for (int j = 0; j < 4; ++j) acc[i][j] = 0.f;
        }
    }

    for (int ut = 0; ut < VV / TU; ++ut) {
        int u0 = ut * TU;
        __syncthreads();   // St ready (1st iter) / prev tile fully consumed

        // Coefficient generation: 40*32 = 1280 pairs, 10 per thread.
#pragma unroll
        for (int j = 0; j < (TU * VT) / 128; ++j) {
            int idx = tid + j * 128;
            int ul = idx >> 5, vl = idx & 31;
            int u = u0 + ul, v = v0 + vl;
            float c1 = 0.f, c2 = 0.f;
            if (v < VV) {
                float s1 = Snt[(size_t)u * VV + v];   // coalesced over vl
                float s2 = St[vl * 201 + u];          // conflict-free (pad 201)
                float a  = Atn[(size_t)u * VV + v];
                float l  = -fminf(s1, s2);
                float dl = 0.f;
                if (u == v) { l += g_d[(size_t)nt * VV + u] - 1.0f; dl = a; }
                c1 = l * a;
                c2 = 2.f * l * l * a - dl;
            }
            cs1[ul * VT + vl] = c1;
            cs2[ul * VT + vl] = c2;
        }
        // Stage y tiles
        const float* y1p = g_y1 + ((size_t)nt * VV + u0) * FOUT;
        const float* y2p = g_y2 + ((size_t)nt * VV + u0) * FOUT;
        for (int i = tid; i < TU * 64; i += 128) {
            ys1[i] = y1p[i];
            ys2[i] = y2p[i];
        }
        __syncthreads();

        // Main FMA loop: 4v x 4fo x 2k per u
#pragma unroll 8
        for (int ul = 0; ul < TU; ++ul) {
            float4 c1v = *(const float4*)(cs1 + ul * VT + (vr << 2));
            float4 c2v = *(const float4*)(cs2 + ul * VT + (vr << 2));
            float4 y1v = *(const float4*)(ys1 + (ul << 6) + (fq << 2));
            float4 y2v = *(const float4*)(ys2 + (ul << 6) + (fq << 2));
            float c1a[4] = {c1v.x, c1v.y, c1v.z, c1v.w};
            float c2a[4] = {c2v.x, c2v.y, c2v.z, c2v.w};
            float y1a[4] = {y1v.x, y1v.y, y1v.z, y1v.w};
            float y2a[4] = {y2v.x, y2v.y, y2v.z, y2v.w};
#pragma unroll
            for (int i = 0; i < 4; ++i)
#pragma unroll
                for (int j = 0; j < 4; ++j)
                    acc[i][j] += c1a[i] * y1a[j] + c2a[i] * y2a[j];
        }
    }

    // relu + store
#pragma unroll
    for (int i = 0; i < 4; ++i) {
        int v = v0 + vr * 4 + i;
        if (v < VV) {
            float* op = out + ((size_t)nt * VV + v) * FOUT + fq * 4;
#pragma unroll
            for (int j = 0; j < 4; ++j) op[j] = fmaxf(acc[i][j], 0.f);
        }
    }
}

// ---------------------------------------------------------------------------
extern "C" void kernel_launch(void* const* d_in, const int* in_sizes, int n_in,
                              void* d_out, int out_size) {
    (void)in_sizes; (void)n_in; (void)out_size;
    const float* x     = (const float*)d_in[0];
    const float* Att   = (const float*)d_in[1];
    const float* S     = (const float*)d_in[2];
    const float* Theta = (const float*)d_in[3];
    float* out = (float*)d_out;

    const int smemA = (3 * 64 * 64 + 32 * 64) * 4;                        // 57344
    const int smemB = (32 * 201 + 2 * TU * VT + 2 * TU * 64) * 4;         // 56448
    cudaFuncSetAttribute(kernelA, cudaFuncAttributeMaxDynamicSharedMemorySize, smemA);
    cudaFuncSetAttribute(kernelB, cudaFuncAttributeMaxDynamicSharedMemorySize, smemB);

    kernelD<<<NT, 256>>>(S);
    kernelA<<<dim3(7, NT), 256, smemA>>>(x, Att, Theta, out);
    kernelB<<<dim3(7, NT), 128, smemB>>>(Att, S, out);
}

// round 2
// speedup vs baseline: 1.4842x; 1.4842x over previous
#include <cuda_runtime.h>

#define NN 8
#define TT 64
#define VV 200
#define FF 64
#define FOUT 64
#define NT (NN*TT)   // 512

typedef unsigned long long u64;

__device__ __forceinline__ u64 pack2(float x, float y) {
    u64 r; asm("mov.b64 %0, {%1,%2};" : "=l"(r) : "f"(x), "f"(y)); return r;
}
__device__ __forceinline__ float2 unpack2(u64 v) {
    float2 f; asm("mov.b64 {%0,%1}, %2;" : "=f"(f.x), "=f"(f.y) : "l"(v)); return f;
}
__device__ __forceinline__ u64 ffma2(u64 a, u64 b, u64 c) {
    u64 d; asm("fma.rn.f32x2 %0, %1, %2, %3;" : "=l"(d) : "l"(a), "l"(b), "l"(c)); return d;
}

// scratch (static device globals; no runtime allocation)
__device__ __align__(16) float g_y1[(size_t)NT*VV*FOUT];
__device__ __align__(16) float g_y2[(size_t)NT*VV*FOUT];
__device__ __align__(16) float g_msym[(size_t)NT*VV*VV];
__device__ float g_d[(size_t)NT*VV];

// ---------------------------------------------------------------------------
// kernelDM: msym[nt,u,v] = min(S[nt,u,v], S[nt,v,u]);  d[nt,u] = sum_v msym
// Fully coalesced both directions via 32x33 transpose tile. block (32,8).
// grid (NT, 7) — u-stripes of 32 (last stripe 8 rows).
// ---------------------------------------------------------------------------
__global__ void kernelDM(const float* __restrict__ S) {
    __shared__ float T[32][33];
    int nt = blockIdx.x;
    int u0 = blockIdx.y * 32;
    int uw = (VV - u0 < 32) ? (VV - u0) : 32;
    int tx = threadIdx.x;   // 0..31
    int ty = threadIdx.y;   // 0..7
    const float* Snt = S + (size_t)nt * VV * VV;
    float* Mnt = g_msym + (size_t)nt * VV * VV;

    float dacc[4] = {0.f, 0.f, 0.f, 0.f};
    for (int v0 = 0; v0 < VV; v0 += 32) {
        int vw = (VV - v0 < 32) ? (VV - v0) : 32;
        __syncthreads();
        // transpose tile: T[vy][ux] = S[v0+vy][u0+ux] (coalesced along ux)
        if (tx < uw)
            for (int vy = ty; vy < vw; vy += 8)
                T[vy][tx] = Snt[(size_t)(v0 + vy) * VV + u0 + tx];
        __syncthreads();
        if (tx < vw) {
#pragma unroll
            for (int k = 0; k < 4; ++k) {
                int uy = ty + k * 8;
                if (uy < uw) {
                    float a = Snt[(size_t)(u0 + uy) * VV + v0 + tx]; // coalesced
                    float m = fminf(a, T[tx][uy]);                   // conflict-free
                    Mnt[(size_t)(u0 + uy) * VV + v0 + tx] = m;       // coalesced
                    dacc[k] += m;
                }
            }
        }
    }
#pragma unroll
    for (int off = 16; off; off >>= 1)
#pragma unroll
        for (int k = 0; k < 4; ++k)
            dacc[k] += __shfl_down_sync(0xffffffffu, dacc[k], off);
    if (tx == 0)
#pragma unroll
        for (int k = 0; k < 4; ++k) {
            int uy = ty + k * 8;
            if (uy < uw) g_d[(size_t)nt * VV + u0 + uy] = dacc[k];
        }
}

// ---------------------------------------------------------------------------
// kernelA: y1 = x@Theta1, y2 = x@Theta2, base = Att[u,u]*(x@Theta0) -> out
// grid (5, NT), 160 threads; thread tile = 2 u-rows x 8 fo (4 f32x2 pairs) x 3k.
// ---------------------------------------------------------------------------
__global__ void __launch_bounds__(160, 3) kernelA(
        const float* __restrict__ x,
        const float* __restrict__ Att,
        const float* __restrict__ Theta,
        float* __restrict__ out_base) {
    extern __shared__ __align__(16) float sA[];
    float* Th = sA;                 // 3*64*64 = 12288 floats
    float* xs = sA + 3 * 64 * 64;   // 40*65 (padded) = 2600 floats

    int u0  = blockIdx.x * 40;
    int nt  = blockIdx.y;
    int n   = nt / TT;
    int tid = threadIdx.x;

    { // stage Theta (48KB) as float4
        const float4* Tg = (const float4*)Theta;
        float4* Ts = (float4*)Th;
        for (int i = tid; i < 3 * 64 * 64 / 4; i += 160) Ts[i] = Tg[i];
    }
    { // stage x rows [u0, u0+40), stride padded to 65
        const float* xnt = x + (size_t)nt * VV * FF;
        for (int i = tid; i < 40 * 64; i += 160) {
            int r = i >> 6, c = i & 63;
            xs[r * 65 + c] = xnt[(size_t)(u0 + r) * FF + c];
        }
    }
    __syncthreads();

    int fo8 = tid & 7;      // fo group of 8
    int ug  = tid >> 3;     // 0..19, two u rows each
    const float* x0 = xs + (ug * 2) * 65;
    const float* x1 = x0 + 65;

    u64 acc[3][2][4];
#pragma unroll
    for (int k = 0; k < 3; ++k)
#pragma unroll
        for (int r = 0; r < 2; ++r)
#pragma unroll
            for (int j = 0; j < 4; ++j) acc[k][r][j] = 0ull;

    const ulonglong2* Tp = (const ulonglong2*)Th;  // 4 floats per ulonglong2
#pragma unroll 8
    for (int f = 0; f < 64; ++f) {
        u64 xv0 = pack2(x0[f], x0[f]);
        u64 xv1 = pack2(x1[f], x1[f]);
        int base = (f * 64 + fo8 * 8) >> 2;        // ulonglong2 index
#pragma unroll
        for (int k = 0; k < 3; ++k) {
            ulonglong2 ta = Tp[base + k * 1024];
            ulonglong2 tb = Tp[base + k * 1024 + 1];
            acc[k][0][0] = ffma2(xv0, ta.x, acc[k][0][0]);
            acc[k][0][1] = ffma2(xv0, ta.y, acc[k][0][1]);
            acc[k][0][2] = ffma2(xv0, tb.x, acc[k][0][2]);
            acc[k][0][3] = ffma2(xv0, tb.y, acc[k][0][3]);
            acc[k][1][0] = ffma2(xv1, ta.x, acc[k][1][0]);
            acc[k][1][1] = ffma2(xv1, ta.y, acc[k][1][1]);
            acc[k][1][2] = ffma2(xv1, tb.x, acc[k][1][2]);
            acc[k][1][3] = ffma2(xv1, tb.y, acc[k][1][3]);
        }
    }

#pragma unroll
    for (int r = 0; r < 2; ++r) {
        int u = u0 + ug * 2 + r;
        size_t ob = ((size_t)nt * VV + u) * FOUT + fo8 * 8;
        float att = Att[((size_t)n * VV + u) * VV + u];
        float4 o0, o1;
        float2 p;
        p = unpack2(acc[0][r][0]); o0.x = att * p.x; o0.y = att * p.y;
        p = unpack2(acc[0][r][1]); o0.z = att * p.x; o0.w = att * p.y;
        p = unpack2(acc[0][r][2]); o1.x = att * p.x; o1.y = att * p.y;
        p = unpack2(acc[0][r][3]); o1.z = att * p.x; o1.w = att * p.y;
        *(float4*)(out_base + ob)     = o0;
        *(float4*)(out_base + ob + 4) = o1;
        *(ulonglong2*)(g_y1 + ob)     = make_ulonglong2(acc[1][r][0], acc[1][r][1]);
        *(ulonglong2*)(g_y1 + ob + 4) = make_ulonglong2(acc[1][r][2], acc[1][r][3]);
        *(ulonglong2*)(g_y2 + ob)     = make_ulonglong2(acc[2][r][0], acc[2][r][1]);
        *(ulonglong2*)(g_y2 + ob + 4) = make_ulonglong2(acc[2][r][2], acc[2][r][3]);
    }
}

// ---------------------------------------------------------------------------
// kernelB: out[v,fo] = relu( base + sum_u c1[u,v]*y1[u,fo] + c2[u,v]*y2[u,fo] )
//   c1 = l*Att[u,v],  c2 = (2l^2 - d_uv)*Att[u,v],  l = (u==v? d[u]-1:0) - msym
// grid (5, NT), 160 threads; thread tile 4v x 4fo; coeffs duplicated in smem
// so both FFMA2 operands come straight from LDS.128 (no pack movs).
// ---------------------------------------------------------------------------
__global__ void kernelB(const float* __restrict__ Att, float* __restrict__ out) {
    __shared__ __align__(16) float cs1d[25 * 80];   // [ul][2*vl] duplicated
    __shared__ __align__(16) float cs2d[25 * 80];
    __shared__ __align__(16) float ys1[25 * 64];
    __shared__ __align__(16) float ys2[25 * 64];

    int v0 = blockIdx.x * 40;
    int nt = blockIdx.y;
    int n  = nt / TT;
    int tid = threadIdx.x;      // 160
    int vr = tid >> 4;          // 0..9 -> v = v0 + 4*vr + i
    int fq = tid & 15;          // 0..15 -> fo = 4*fq + j

    const float* Mnt = g_msym + (size_t)nt * VV * VV;
    const float* Atn = Att + (size_t)n * VV * VV;
    const float* dnt = g_d + (size_t)nt * VV;

    u64 acc[4][2];
    size_t obase = ((size_t)nt * VV + v0 + vr * 4) * FOUT + fq * 4;
#pragma unroll
    for (int i = 0; i < 4; ++i) {
        ulonglong2 t = *(const ulonglong2*)(out + obase + i * FOUT);
        acc[i][0] = t.x; acc[i][1] = t.y;
    }

    for (int ut = 0; ut < 8; ++ut) {
        int u0 = ut * 25;
        __syncthreads();
        // coefficient generation: 25u x 40v, written duplicated as f32x2
        for (int idx = tid; idx < 25 * 40; idx += 160) {
            int ul = idx / 40, vl = idx - ul * 40;
            int u = u0 + ul, v = v0 + vl;
            float m = Mnt[(size_t)u * VV + v];        // coalesced
            float a = Atn[(size_t)u * VV + v];
            float l = -m;
            float dl = 0.f;
            if (u == v) { l += dnt[u] - 1.0f; dl = a; }
            float c1 = l * a;
            float c2 = 2.f * l * l * a - dl;
            ((u64*)cs1d)[ul * 40 + vl] = pack2(c1, c1);
            ((u64*)cs2d)[ul * 40 + vl] = pack2(c2, c2);
        }
        // stage y tiles (25x64 each)
        const float4* y1g = (const float4*)(g_y1 + ((size_t)nt * VV + u0) * FOUT);
        const float4* y2g = (const float4*)(g_y2 + ((size_t)nt * VV + u0) * FOUT);
        for (int i = tid; i < 25 * 16; i += 160) {
            ((float4*)ys1)[i] = y1g[i];
            ((float4*)ys2)[i] = y2g[i];
        }
        __syncthreads();

#pragma unroll 5
        for (int ul = 0; ul < 25; ++ul) {
            const ulonglong2* c1p = (const ulonglong2*)((const u64*)cs1d + ul * 40 + vr * 4);
            const ulonglong2* c2p = (const ulonglong2*)((const u64*)cs2d + ul * 40 + vr * 4);
            ulonglong2 c1a = c1p[0], c1b = c1p[1];
            ulonglong2 c2a = c2p[0], c2b = c2p[1];
            ulonglong2 y1 = *(const ulonglong2*)((const u64*)ys1 + ul * 32 + fq * 2);
            ulonglong2 y2 = *(const ulonglong2*)((const u64*)ys2 + ul * 32 + fq * 2);
            acc[0][0] = ffma2(c1a.x, y1.x, acc[0][0]);
            acc[0][1] = ffma2(c1a.x, y1.y, acc[0][1]);
            acc[1][0] = ffma2(c1a.y, y1.x, acc[1][0]);
            acc[1][1] = ffma2(c1a.y, y1.y, acc[1][1]);
            acc[2][0] = ffma2(c1b.x, y1.x, acc[2][0]);
            acc[2][1] = ffma2(c1b.x, y1.y, acc[2][1]);
            acc[3][0] = ffma2(c1b.y, y1.x, acc[3][0]);
            acc[3][1] = ffma2(c1b.y, y1.y, acc[3][1]);
            acc[0][0] = ffma2(c2a.x, y2.x, acc[0][0]);
            acc[0][1] = ffma2(c2a.x, y2.y, acc[0][1]);
            acc[1][0] = ffma2(c2a.y, y2.x, acc[1][0]);
            acc[1][1] = ffma2(c2a.y, y2.y, acc[1][1]);
            acc[2][0] = ffma2(c2b.x, y2.x, acc[2][0]);
            acc[2][1] = ffma2(c2b.x, y2.y, acc[2][1]);
            acc[3][0] = ffma2(c2b.y, y2.x, acc[3][0]);
            acc[3][1] = ffma2(c2b.y, y2.y, acc[3][1]);
        }
    }

    // relu + store
#pragma unroll
    for (int i = 0; i < 4; ++i) {
        float2 p0 = unpack2(acc[i][0]);
        float2 p1 = unpack2(acc[i][1]);
        float4 o;
        o.x = fmaxf(p0.x, 0.f); o.y = fmaxf(p0.y, 0.f);
        o.z = fmaxf(p1.x, 0.f); o.w = fmaxf(p1.y, 0.f);
        *(float4*)(out + obase + i * FOUT) = o;
    }
}

// ---------------------------------------------------------------------------
extern "C" void kernel_launch(void* const* d_in, const int* in_sizes, int n_in,
                              void* d_out, int out_size) {
    (void)in_sizes; (void)n_in; (void)out_size;
    const float* x     = (const float*)d_in[0];
    const float* Att   = (const float*)d_in[1];
    const float* S     = (const float*)d_in[2];
    const float* Theta = (const float*)d_in[3];
    float* out = (float*)d_out;

    const int smemA = (3 * 64 * 64 + 40 * 65) * 4;   // 59552
    cudaFuncSetAttribute(kernelA, cudaFuncAttributeMaxDynamicSharedMemorySize, smemA);

    kernelDM<<<dim3(NT, 7), dim3(32, 8)>>>(S);
    kernelA<<<dim3(5, NT), 160, smemA>>>(x, Att, Theta, out);
    kernelB<<<dim3(5, NT), 160>>>(Att, out);
}

// round 4
// speedup vs baseline: 1.6748x; 1.1284x over previous
#include <cuda_runtime.h>
#include <cstdint>

#define NN 8
#define TT 64
#define VV 200
#define FF 64
#define FOUT 64
#define NT (NN*TT)   // 512

typedef unsigned long long u64;

__device__ __forceinline__ u64 pack2(float x, float y) {
    u64 r; asm("mov.b64 %0, {%1,%2};" : "=l"(r) : "f"(x), "f"(y)); return r;
}
__device__ __forceinline__ float2 unpack2(u64 v) {
    float2 f; asm("mov.b64 {%0,%1}, %2;" : "=f"(f.x), "=f"(f.y) : "l"(v)); return f;
}
__device__ __forceinline__ u64 ffma2(u64 a, u64 b, u64 c) {
    u64 d; asm("fma.rn.f32x2 %0, %1, %2, %3;" : "=l"(d) : "l"(a), "l"(b), "l"(c)); return d;
}
__device__ __forceinline__ void cpa16(unsigned int dst, const void* src) {
    asm volatile("cp.async.cg.shared.global [%0], [%1], 16;" :: "r"(dst), "l"(src));
}
#define CP_COMMIT() asm volatile("cp.async.commit_group;" ::: "memory")
#define CP_WAIT_ALL() asm volatile("cp.async.wait_group 0;" ::: "memory")

// scratch (static device globals; no runtime allocation)
__device__ __align__(16) float g_y1[(size_t)NT*VV*FOUT];
__device__ __align__(16) float g_y2[(size_t)NT*VV*FOUT];
__device__ __align__(16) float g_msym[(size_t)NT*VV*VV];
__device__ float g_d[(size_t)NT*VV];

// ---------------------------------------------------------------------------
// kernelDM: msym[nt,u,v] = min(S[nt,u,v], S[nt,v,u]);  d[nt,u] = sum_v msym
// ---------------------------------------------------------------------------
__global__ void kernelDM(const float* __restrict__ S) {
    __shared__ float T[32][33];
    int nt = blockIdx.x;
    int u0 = blockIdx.y * 32;
    int uw = (VV - u0 < 32) ? (VV - u0) : 32;
    int tx = threadIdx.x;   // 0..31
    int ty = threadIdx.y;   // 0..7
    const float* Snt = S + (size_t)nt * VV * VV;
    float* Mnt = g_msym + (size_t)nt * VV * VV;

    float dacc[4] = {0.f, 0.f, 0.f, 0.f};
    for (int v0 = 0; v0 < VV; v0 += 32) {
        int vw = (VV - v0 < 32) ? (VV - v0) : 32;
        __syncthreads();
        if (tx < uw)
            for (int vy = ty; vy < vw; vy += 8)
                T[vy][tx] = Snt[(size_t)(v0 + vy) * VV + u0 + tx];
        __syncthreads();
        if (tx < vw) {
#pragma unroll
            for (int k = 0; k < 4; ++k) {
                int uy = ty + k * 8;
                if (uy < uw) {
                    float a = Snt[(size_t)(u0 + uy) * VV + v0 + tx];
                    float m = fminf(a, T[tx][uy]);
                    Mnt[(size_t)(u0 + uy) * VV + v0 + tx] = m;
                    dacc[k] += m;
                }
            }
        }
    }
#pragma unroll
    for (int off = 16; off; off >>= 1)
#pragma unroll
        for (int k = 0; k < 4; ++k)
            dacc[k] += __shfl_down_sync(0xffffffffu, dacc[k], off);
    if (tx == 0)
#pragma unroll
        for (int k = 0; k < 4; ++k) {
            int uy = ty + k * 8;
            if (uy < uw) g_d[(size_t)nt * VV + u0 + uy] = dacc[k];
        }
}

// ---------------------------------------------------------------------------
// kernelA: y1 = x@Theta1, y2 = x@Theta2, base = Att[u,u]*(x@Theta0) -> out
// ---------------------------------------------------------------------------
__global__ void __launch_bounds__(160, 3) kernelA(
        const float* __restrict__ x,
        const float* __restrict__ Att,
        const float* __restrict__ Theta,
        float* __restrict__ out_base) {
    extern __shared__ __align__(16) float sA[];
    float* Th = sA;                 // 3*64*64
    float* xs = sA + 3 * 64 * 64;   // 40*65 padded

    int u0  = blockIdx.x * 40;
    int nt  = blockIdx.y;
    int n   = nt / TT;
    int tid = threadIdx.x;

    {
        const float4* Tg = (const float4*)Theta;
        float4* Ts = (float4*)Th;
        for (int i = tid; i < 3 * 64 * 64 / 4; i += 160) Ts[i] = Tg[i];
    }
    {
        const float* xnt = x + (size_t)nt * VV * FF;
        for (int i = tid; i < 40 * 64; i += 160) {
            int r = i >> 6, c = i & 63;
            xs[r * 65 + c] = xnt[(size_t)(u0 + r) * FF + c];
        }
    }
    __syncthreads();

    int fo8 = tid & 7;
    int ug  = tid >> 3;
    const float* x0 = xs + (ug * 2) * 65;
    const float* x1 = x0 + 65;

    u64 acc[3][2][4];
#pragma unroll
    for (int k = 0; k < 3; ++k)
#pragma unroll
        for (int r = 0; r < 2; ++r)
#pragma unroll
            for (int j = 0; j < 4; ++j) acc[k][r][j] = 0ull;

    const ulonglong2* Tp = (const ulonglong2*)Th;
#pragma unroll 8
    for (int f = 0; f < 64; ++f) {
        u64 xv0 = pack2(x0[f], x0[f]);
        u64 xv1 = pack2(x1[f], x1[f]);
        int base = (f * 64 + fo8 * 8) >> 2;
#pragma unroll
        for (int k = 0; k < 3; ++k) {
            ulonglong2 ta = Tp[base + k * 1024];
            ulonglong2 tb = Tp[base + k * 1024 + 1];
            acc[k][0][0] = ffma2(xv0, ta.x, acc[k][0][0]);
            acc[k][0][1] = ffma2(xv0, ta.y, acc[k][0][1]);
            acc[k][0][2] = ffma2(xv0, tb.x, acc[k][0][2]);
            acc[k][0][3] = ffma2(xv0, tb.y, acc[k][0][3]);
            acc[k][1][0] = ffma2(xv1, ta.x, acc[k][1][0]);
            acc[k][1][1] = ffma2(xv1, ta.y, acc[k][1][1]);
            acc[k][1][2] = ffma2(xv1, tb.x, acc[k][1][2]);
            acc[k][1][3] = ffma2(xv1, tb.y, acc[k][1][3]);
        }
    }

#pragma unroll
    for (int r = 0; r < 2; ++r) {
        int u = u0 + ug * 2 + r;
        size_t ob = ((size_t)nt * VV + u) * FOUT + fo8 * 8;
        float att = Att[((size_t)n * VV + u) * VV + u];
        float4 o0, o1;
        float2 p;
        p = unpack2(acc[0][r][0]); o0.x = att * p.x; o0.y = att * p.y;
        p = unpack2(acc[0][r][1]); o0.z = att * p.x; o0.w = att * p.y;
        p = unpack2(acc[0][r][2]); o1.x = att * p.x; o1.y = att * p.y;
        p = unpack2(acc[0][r][3]); o1.z = att * p.x; o1.w = att * p.y;
        *(float4*)(out_base + ob)     = o0;
        *(float4*)(out_base + ob + 4) = o1;
        *(ulonglong2*)(g_y1 + ob)     = make_ulonglong2(acc[1][r][0], acc[1][r][1]);
        *(ulonglong2*)(g_y1 + ob + 4) = make_ulonglong2(acc[1][r][2], acc[1][r][3]);
        *(ulonglong2*)(g_y2 + ob)     = make_ulonglong2(acc[2][r][0], acc[2][r][1]);
        *(ulonglong2*)(g_y2 + ob + 4) = make_ulonglong2(acc[2][r][2], acc[2][r][3]);
    }
}

// ---------------------------------------------------------------------------
// kernelB v3: cp.async double-buffered pipeline, 64 threads (2 warps).
// Block tile: 40v x 64fo, thread tile 5v x 8fo, u-chunks of 10.
// ---------------------------------------------------------------------------
#define TUB 10
__global__ void __launch_bounds__(64) kernelB(const float* __restrict__ Att,
                                              float* __restrict__ out) {
    __shared__ __align__(16) float sm_m [2][TUB * 40];
    __shared__ __align__(16) float sm_a [2][TUB * 40];
    __shared__ __align__(16) float sm_y1[2][TUB * 64];
    __shared__ __align__(16) float sm_y2[2][TUB * 64];
    __shared__ __align__(16) u64   sm_c1[TUB * 40];
    __shared__ __align__(16) u64   sm_c2[TUB * 40];

    int v0 = blockIdx.x * 40;
    int nt = blockIdx.y;
    int n  = nt / TT;
    int tid = threadIdx.x;          // 64
    int wid = tid >> 5;
    int lane = tid & 31;
    int vr = lane >> 2;             // 0..7 -> v = v0 + vr*5 + i
    int fq = lane & 3;              // fo = wid*32 + fq*8 + j
    int foff = wid * 32 + fq * 8;

    const float* Mnt = g_msym + (size_t)nt * VV * VV;
    const float* Atn = Att + (size_t)n * VV * VV;
    const float* y1g = g_y1 + (size_t)nt * VV * FOUT;
    const float* y2g = g_y2 + (size_t)nt * VV * FOUT;
    const float* dnt = g_d + (size_t)nt * VV;

    // acc init from kernelA's base term
    u64 acc[5][4];
    size_t obase = ((size_t)nt * VV + v0 + vr * 5) * FOUT + foff;
#pragma unroll
    for (int i = 0; i < 5; ++i) {
        ulonglong2 t = *(const ulonglong2*)(out + obase + (size_t)i * FOUT);
        ulonglong2 s = *(const ulonglong2*)(out + obase + (size_t)i * FOUT + 4);
        acc[i][0] = t.x; acc[i][1] = t.y; acc[i][2] = s.x; acc[i][3] = s.y;
    }

    // ---- staging lambda (cp.async 16B) ----
    auto stage = [&](int ut, int b) {
        int ub = ut * TUB;
        for (int i = tid; i < TUB * 10; i += 64) {
            int r = i / 10, s = i - r * 10;
            const float* msrc = Mnt + (size_t)(ub + r) * VV + v0 + s * 4;
            const float* asrc = Atn + (size_t)(ub + r) * VV + v0 + s * 4;
            cpa16((unsigned int)__cvta_generic_to_shared(&sm_m[b][r * 40 + s * 4]), msrc);
            cpa16((unsigned int)__cvta_generic_to_shared(&sm_a[b][r * 40 + s * 4]), asrc);
        }
        for (int i = tid; i < TUB * 16; i += 64) {
            int r = i >> 4, s = i & 15;
            cpa16((unsigned int)__cvta_generic_to_shared(&sm_y1[b][r * 64 + s * 4]),
                  y1g + (size_t)(ub + r) * FOUT + s * 4);
            cpa16((unsigned int)__cvta_generic_to_shared(&sm_y2[b][r * 64 + s * 4]),
                  y2g + (size_t)(ub + r) * FOUT + s * 4);
        }
        CP_COMMIT();
    };

    stage(0, 0);

    for (int ut = 0; ut < VV / TUB; ++ut) {
        int b = ut & 1;
        int u0 = ut * TUB;
        CP_WAIT_ALL();
        __syncthreads();                 // buf b ready; prev FMA (buf b^1) done

        if (ut + 1 < VV / TUB) stage(ut + 1, b ^ 1);

        // coefficient generation: 400 elems, pre-duplicated u64
        for (int e = tid; e < TUB * 40; e += 64) {
            int ul = e / 40, vl = e - ul * 40;
            int u = u0 + ul, v = v0 + vl;
            float m = sm_m[b][e];
            float a = sm_a[b][e];
            float l = -m, sub = 0.f;
            if (u == v) { l += dnt[u] - 1.0f; sub = a; }
            float c1 = l * a;
            float c2 = 2.f * l * l * a - sub;
            sm_c1[e] = pack2(c1, c1);
            sm_c2[e] = pack2(c2, c2);
        }
        __syncthreads();                 // c ready

        // FMA loop: per u, 40 FFMA2 per thread
#pragma unroll 2
        for (int uu = 0; uu < TUB; ++uu) {
            const u64* c1p = sm_c1 + uu * 40 + vr * 5;
            const u64* c2p = sm_c2 + uu * 40 + vr * 5;
            const ulonglong2* y1p = (const ulonglong2*)(sm_y1[b] + uu * 64 + foff);
            const ulonglong2* y2p = (const ulonglong2*)(sm_y2[b] + uu * 64 + foff);
            ulonglong2 ya = y1p[0], yb = y1p[1];
#pragma unroll
            for (int i = 0; i < 5; ++i) {
                u64 c = c1p[i];
                acc[i][0] = ffma2(c, ya.x, acc[i][0]);
                acc[i][1] = ffma2(c, ya.y, acc[i][1]);
                acc[i][2] = ffma2(c, yb.x, acc[i][2]);
                acc[i][3] = ffma2(c, yb.y, acc[i][3]);
            }
            ya = y2p[0]; yb = y2p[1];
#pragma unroll
            for (int i = 0; i < 5; ++i) {
                u64 c = c2p[i];
                acc[i][0] = ffma2(c, ya.x, acc[i][0]);
                acc[i][1] = ffma2(c, ya.y, acc[i][1]);
                acc[i][2] = ffma2(c, yb.x, acc[i][2]);
                acc[i][3] = ffma2(c, yb.y, acc[i][3]);
            }
        }
    }

    // relu + store
#pragma unroll
    for (int i = 0; i < 5; ++i) {
        float2 p0 = unpack2(acc[i][0]);
        float2 p1 = unpack2(acc[i][1]);
        float2 p2 = unpack2(acc[i][2]);
        float2 p3 = unpack2(acc[i][3]);
        float4 oA, oB;
        oA.x = fmaxf(p0.x, 0.f); oA.y = fmaxf(p0.y, 0.f);
        oA.z = fmaxf(p1.x, 0.f); oA.w = fmaxf(p1.y, 0.f);
        oB.x = fmaxf(p2.x, 0.f); oB.y = fmaxf(p2.y, 0.f);
        oB.z = fmaxf(p3.x, 0.f); oB.w = fmaxf(p3.y, 0.f);
        *(float4*)(out + obase + (size_t)i * FOUT)     = oA;
        *(float4*)(out + obase + (size_t)i * FOUT + 4) = oB;
    }
}

// ---------------------------------------------------------------------------
extern "C" void kernel_launch(void* const* d_in, const int* in_sizes, int n_in,
                              void* d_out, int out_size) {
    (void)in_sizes; (void)n_in; (void)out_size;
    const float* x     = (const float*)d_in[0];
    const float* Att   = (const float*)d_in[1];
    const float* S     = (const float*)d_in[2];
    const float* Theta = (const float*)d_in[3];
    float* out = (float*)d_out;

    const int smemA = (3 * 64 * 64 + 40 * 65) * 4;
    cudaFuncSetAttribute(kernelA, cudaFuncAttributeMaxDynamicSharedMemorySize, smemA);

    kernelDM<<<dim3(NT, 7), dim3(32, 8)>>>(S);
    kernelA<<<dim3(5, NT), 160, smemA>>>(x, Att, Theta, out);
    kernelB<<<dim3(5, NT), 64>>>(Att, out);
}

// round 6
// speedup vs baseline: 2.0234x; 1.2081x over previous
#include <cuda_runtime.h>
#include <cstdint>

#define NN 8
#define TT 64
#define VV 200
#define FF 64
#define FOUT 64
#define NT 512
#define KC 32          // u per chunk in kernelBtc
#define NCH 7          // chunks: 6 full (32u) + 1 partial (8u)

typedef unsigned long long u64;
typedef unsigned int u32;

__device__ __forceinline__ u64 pack2(float x, float y) {
    u64 r; asm("mov.b64 %0, {%1,%2};" : "=l"(r) : "f"(x), "f"(y)); return r;
}
__device__ __forceinline__ float2 unpack2(u64 v) {
    float2 f; asm("mov.b64 {%0,%1}, %2;" : "=f"(f.x), "=f"(f.y) : "l"(v)); return f;
}
__device__ __forceinline__ u64 ffma2(u64 a, u64 b, u64 c) {
    u64 d; asm("fma.rn.f32x2 %0, %1, %2, %3;" : "=l"(d) : "l"(a), "l"(b), "l"(c)); return d;
}
__device__ __forceinline__ void cpa16(u32 dst, const void* src) {
    asm volatile("cp.async.cg.shared.global [%0], [%1], 16;" :: "r"(dst), "l"(src));
}
#define CP_COMMIT()   asm volatile("cp.async.commit_group;" ::: "memory")
#define CP_WAIT_ALL() asm volatile("cp.async.wait_group 0;" ::: "memory")

// TF32 mma: D += A*B, acc in-place. a,b are f32 bit patterns (HW uses tf32 bits).
__device__ __forceinline__ void mma8(float* d, const float* a, const float* bf) {
    asm volatile(
        "mma.sync.aligned.m16n8k8.row.col.f32.tf32.tf32.f32 "
        "{%0,%1,%2,%3},{%4,%5,%6,%7},{%8,%9},{%0,%1,%2,%3};"
        : "+f"(d[0]), "+f"(d[1]), "+f"(d[2]), "+f"(d[3])
        : "r"(__float_as_uint(a[0])), "r"(__float_as_uint(a[1])),
          "r"(__float_as_uint(a[2])), "r"(__float_as_uint(a[3])),
          "r"(__float_as_uint(bf[0])), "r"(__float_as_uint(bf[1])));
}

// scratch (static device globals; no runtime allocation)
__device__ __align__(16) float g_y1[(size_t)NT*VV*FOUT];
__device__ __align__(16) float g_y2[(size_t)NT*VV*FOUT];
__device__ __align__(16) float g_msym[(size_t)NT*VV*VV];
__device__ float g_d[(size_t)NT*VV];

// ---------------------------------------------------------------------------
// kernelDM: msym = min(S, S^T); d = row sums
// ---------------------------------------------------------------------------
__global__ void kernelDM(const float* __restrict__ S) {
    __shared__ float T[32][33];
    int nt = blockIdx.x;
    int u0 = blockIdx.y * 32;
    int uw = (VV - u0 < 32) ? (VV - u0) : 32;
    int tx = threadIdx.x, ty = threadIdx.y;
    const float* Snt = S + (size_t)nt * VV * VV;
    float* Mnt = g_msym + (size_t)nt * VV * VV;

    float dacc[4] = {0.f, 0.f, 0.f, 0.f};
    for (int v0 = 0; v0 < VV; v0 += 32) {
        int vw = (VV - v0 < 32) ? (VV - v0) : 32;
        __syncthreads();
        if (tx < uw)
            for (int vy = ty; vy < vw; vy += 8)
                T[vy][tx] = Snt[(size_t)(v0 + vy) * VV + u0 + tx];
        __syncthreads();
        if (tx < vw) {
#pragma unroll
            for (int k = 0; k < 4; ++k) {
                int uy = ty + k * 8;
                if (uy < uw) {
                    float a = Snt[(size_t)(u0 + uy) * VV + v0 + tx];
                    float m = fminf(a, T[tx][uy]);
                    Mnt[(size_t)(u0 + uy) * VV + v0 + tx] = m;
                    dacc[k] += m;
                }
            }
        }
    }
#pragma unroll
    for (int off = 16; off; off >>= 1)
#pragma unroll
        for (int k = 0; k < 4; ++k)
            dacc[k] += __shfl_down_sync(0xffffffffu, dacc[k], off);
    if (tx == 0)
#pragma unroll
        for (int k = 0; k < 4; ++k) {
            int uy = ty + k * 8;
            if (uy < uw) g_d[(size_t)nt * VV + u0 + uy] = dacc[k];
        }
}

// ---------------------------------------------------------------------------
// kernelA: y1/y2 = x@Theta{1,2} ([u][fo] layout); base = full diagonal term
//          (k=0,1,2 diag contributions, exact fp32) -> out
// ---------------------------------------------------------------------------
__global__ void __launch_bounds__(160, 3) kernelA(
        const float* __restrict__ x,
        const float* __restrict__ Att,
        const float* __restrict__ Theta,
        float* __restrict__ out_base) {
    extern __shared__ __align__(16) float sA[];
    float* Th = sA;                 // 3*64*64
    float* xs = sA + 3 * 64 * 64;   // 40*65 padded

    int u0  = blockIdx.x * 40;
    int nt  = blockIdx.y;
    int n   = nt / TT;
    int tid = threadIdx.x;

    {
        const float4* Tg = (const float4*)Theta;
        float4* Ts = (float4*)Th;
        for (int i = tid; i < 3 * 64 * 64 / 4; i += 160) Ts[i] = Tg[i];
    }
    {
        const float* xnt = x + (size_t)nt * VV * FF;
        for (int i = tid; i < 40 * 64; i += 160) {
            int r = i >> 6, c = i & 63;
            xs[r * 65 + c] = xnt[(size_t)(u0 + r) * FF + c];
        }
    }
    __syncthreads();

    int fo8 = tid & 7;
    int ug  = tid >> 3;
    const float* x0 = xs + (ug * 2) * 65;
    const float* x1 = x0 + 65;

    u64 acc[3][2][4];
#pragma unroll
    for (int k = 0; k < 3; ++k)
#pragma unroll
        for (int r = 0; r < 2; ++r)
#pragma unroll
            for (int j = 0; j < 4; ++j) acc[k][r][j] = 0ull;

    const ulonglong2* Tp = (const ulonglong2*)Th;
#pragma unroll 8
    for (int f = 0; f < 64; ++f) {
        u64 xv0 = pack2(x0[f], x0[f]);
        u64 xv1 = pack2(x1[f], x1[f]);
        int base = (f * 64 + fo8 * 8) >> 2;
#pragma unroll
        for (int k = 0; k < 3; ++k) {
            ulonglong2 ta = Tp[base + k * 1024];
            ulonglong2 tb = Tp[base + k * 1024 + 1];
            acc[k][0][0] = ffma2(xv0, ta.x, acc[k][0][0]);
            acc[k][0][1] = ffma2(xv0, ta.y, acc[k][0][1]);
            acc[k][0][2] = ffma2(xv0, tb.x, acc[k][0][2]);
            acc[k][0][3] = ffma2(xv0, tb.y, acc[k][0][3]);
            acc[k][1][0] = ffma2(xv1, ta.x, acc[k][1][0]);
            acc[k][1][1] = ffma2(xv1, ta.y, acc[k][1][1]);
            acc[k][1][2] = ffma2(xv1, tb.x, acc[k][1][2]);
            acc[k][1][3] = ffma2(xv1, tb.y, acc[k][1][3]);
        }
    }

#pragma unroll
    for (int r = 0; r < 2; ++r) {
        int u = u0 + ug * 2 + r;
        float att = Att[((size_t)n * VV + u) * VV + u];
        float duu = g_d[(size_t)nt * VV + u];
        float muu = g_msym[((size_t)nt * VV + u) * VV + u];
        float l = duu - 1.0f - muu;       // L_t diag
        float c1d = l * att;
        float c2d = (2.0f * l * l - 1.0f) * att;

        size_t ob = ((size_t)nt * VV + u) * FOUT + fo8 * 8;
        float ob8[8];
#pragma unroll
        for (int j = 0; j < 4; ++j) {
            float2 p0 = unpack2(acc[0][r][j]);
            float2 p1 = unpack2(acc[1][r][j]);
            float2 p2 = unpack2(acc[2][r][j]);
            ob8[2*j]   = att * p0.x + c1d * p1.x + c2d * p2.x;
            ob8[2*j+1] = att * p0.y + c1d * p1.y + c2d * p2.y;
        }
        *(float4*)(out_base + ob)     = make_float4(ob8[0], ob8[1], ob8[2], ob8[3]);
        *(float4*)(out_base + ob + 4) = make_float4(ob8[4], ob8[5], ob8[6], ob8[7]);
        *(ulonglong2*)(g_y1 + ob)     = make_ulonglong2(acc[1][r][0], acc[1][r][1]);
        *(ulonglong2*)(g_y1 + ob + 4) = make_ulonglong2(acc[1][r][2], acc[1][r][3]);
        *(ulonglong2*)(g_y2 + ob)     = make_ulonglong2(acc[2][r][0], acc[2][r][1]);
        *(ulonglong2*)(g_y2 + ob + 4) = make_ulonglong2(acc[2][r][2], acc[2][r][3]);
    }
}

// ---------------------------------------------------------------------------
// kernelBtc: TF32 mma.sync — out[v,fo] = relu(base + sum_{u!=v} c1*y1 + c2*y2)
// 1 CTA per nt, 224 threads (7 warps), warp w owns v in [32w, 32w+32).
// smem (floats): m[2][32*200] | a[2][32*200] | y1[2][32*72] | y2[2][32*72]
// ---------------------------------------------------------------------------
#define OFF_M  0
#define OFF_A  12800
#define OFF_Y1 25600
#define OFF_Y2 30208
#define SMB_FLOATS 34816    // 139264 bytes

__global__ void __launch_bounds__(224) kernelBtc(const float* __restrict__ Att,
                                                 float* __restrict__ out) {
    extern __shared__ __align__(16) float sm[];
    int nt = blockIdx.x;
    int n  = nt / TT;
    int tid = threadIdx.x;
    int w = tid >> 5, lane = tid & 31;
    int g = lane >> 2, tg = lane & 3;
    int vbase = w * 32;

    const float* Mnt = g_msym + (size_t)nt * VV * VV;
    const float* Atn = Att + (size_t)n * VV * VV;
    const float* y1g = g_y1 + (size_t)nt * VV * FOUT;
    const float* y2g = g_y2 + (size_t)nt * VV * FOUT;

    float acc[2][8][4];
#pragma unroll
    for (int mt = 0; mt < 2; ++mt)
#pragma unroll
        for (int nn = 0; nn < 8; ++nn)
#pragma unroll
            for (int j = 0; j < 4; ++j) acc[mt][nn][j] = 0.f;

    auto stage = [&](int c, int b) {
        int u0 = c * KC;
        int uw = (c == NCH - 1) ? 8 : 32;
        for (int i = tid; i < uw * 50; i += 224) {
            int r = i / 50, s = i - r * 50;
            cpa16((u32)__cvta_generic_to_shared(sm + OFF_M + b * 6400 + r * 200 + s * 4),
                  Mnt + (size_t)(u0 + r) * VV + s * 4);
            cpa16((u32)__cvta_generic_to_shared(sm + OFF_A + b * 6400 + r * 200 + s * 4),
                  Atn + (size_t)(u0 + r) * VV + s * 4);
        }
        for (int i = tid; i < uw * 16; i += 224) {
            int r = i >> 4, s = i & 15;
            cpa16((u32)__cvta_generic_to_shared(sm + OFF_Y1 + b * 2304 + r * 72 + s * 4),
                  y1g + (size_t)(u0 + r) * FOUT + s * 4);
            cpa16((u32)__cvta_generic_to_shared(sm + OFF_Y2 + b * 2304 + r * 72 + s * 4),
                  y2g + (size_t)(u0 + r) * FOUT + s * 4);
        }
        CP_COMMIT();
    };

    stage(0, 0);

    for (int c = 0; c < NCH; ++c) {
        int b = c & 1;
        CP_WAIT_ALL();
        __syncthreads();             // chunk c data ready; all warps past mma(c-1)
        if (c + 1 < NCH) stage(c + 1, b ^ 1);

        int ks = (c == NCH - 1) ? 1 : 4;
        int u0 = c * KC;
        const float* mb  = sm + OFF_M  + b * 6400;
        const float* ab  = sm + OFF_A  + b * 6400;
        const float* y1b = sm + OFF_Y1 + b * 2304;
        const float* y2b = sm + OFF_Y2 + b * 2304;

        for (int k = 0; k < ks; ++k) {
            int cc0 = 8 * k + tg;        // local u col (A) / row (B)
            // ---- A fragments (coefficients inline, diag & OOB zeroed) ----
            float af1[2][4], af2[2][4];
#pragma unroll
            for (int mt = 0; mt < 2; ++mt) {
                int vA = vbase + 16 * mt + g;
                int vB = vA + 8;
                int ug0 = u0 + cc0, ug1 = ug0 + 4;
                int o0 = cc0 * 200, o1 = o0 + 800;   // (cc0+4)*200
                float m0 = mb[o0 + vA], a0 = ab[o0 + vA];
                float m1 = mb[o0 + vB], a1 = ab[o0 + vB];
                float m2 = mb[o1 + vA], a2 = ab[o1 + vA];
                float m3 = mb[o1 + vB], a3 = ab[o1 + vB];
                float am0 = m0 * a0, am1 = m1 * a1, am2 = m2 * a2, am3 = m3 * a3;
                bool k0 = (vA < VV) && (ug0 != vA);
                bool k1 = (vB < VV) && (ug0 != vB);
                bool k2 = (vA < VV) && (ug1 != vA);
                bool k3 = (vB < VV) && (ug1 != vB);
                af1[mt][0] = k0 ? -am0 : 0.f;  af2[mt][0] = k0 ? 2.f * m0 * am0 : 0.f;
                af1[mt][1] = k1 ? -am1 : 0.f;  af2[mt][1] = k1 ? 2.f * m1 * am1 : 0.f;
                af1[mt][2] = k2 ? -am2 : 0.f;  af2[mt][2] = k2 ? 2.f * m2 * am2 : 0.f;
                af1[mt][3] = k3 ? -am3 : 0.f;  af2[mt][3] = k3 ? 2.f * m3 * am3 : 0.f;
            }
            // ---- B fragments ----
            float bf1[8][2], bf2[8][2];
            int r0 = cc0 * 72 + g;
#pragma unroll
            for (int nn = 0; nn < 8; ++nn) {
                bf1[nn][0] = y1b[r0 + 8 * nn];
                bf1[nn][1] = y1b[r0 + 288 + 8 * nn];
                bf2[nn][0] = y2b[r0 + 8 * nn];
                bf2[nn][1] = y2b[r0 + 288 + 8 * nn];
            }
            // ---- 32 HMMA ----
#pragma unroll
            for (int mt = 0; mt < 2; ++mt)
#pragma unroll
                for (int nn = 0; nn < 8; ++nn) {
                    mma8(acc[mt][nn], af1[mt], bf1[nn]);
                    mma8(acc[mt][nn], af2[mt], bf2[nn]);
                }
        }
    }

    // ---- epilogue: base + D, relu, store ----
#pragma unroll
    for (int mt = 0; mt < 2; ++mt) {
        int v0 = vbase + 16 * mt + g;
        int v1 = v0 + 8;
#pragma unroll
        for (int nn = 0; nn < 8; ++nn) {
            int fo = nn * 8 + 2 * tg;
            if (v0 < VV) {
                float* p = out + ((size_t)nt * VV + v0) * FOUT + fo;
                float2 bse = *(const float2*)p;
                float2 o;
                o.x = fmaxf(bse.x + acc[mt][nn][0], 0.f);
                o.y = fmaxf(bse.y + acc[mt][nn][1], 0.f);
                *(float2*)p = o;
            }
            if (v1 < VV) {
                float* p = out + ((size_t)nt * VV + v1) * FOUT + fo;
                float2 bse = *(const float2*)p;
                float2 o;
                o.x = fmaxf(bse.x + acc[mt][nn][2], 0.f);
                o.y = fmaxf(bse.y + acc[mt][nn][3], 0.f);
                *(float2*)p = o;
            }
        }
    }
}

// ---------------------------------------------------------------------------
extern "C" void kernel_launch(void* const* d_in, const int* in_sizes, int n_in,
                              void* d_out, int out_size) {
    (void)in_sizes; (void)n_in; (void)out_size;
    const float* x     = (const float*)d_in[0];
    const float* Att   = (const float*)d_in[1];
    const float* S     = (const float*)d_in[2];
    const float* Theta = (const float*)d_in[3];
    float* out = (float*)d_out;

    const int smemA = (3 * 64 * 64 + 40 * 65) * 4;
    const int smemB = SMB_FLOATS * 4;     // 139264
    cudaFuncSetAttribute(kernelA,   cudaFuncAttributeMaxDynamicSharedMemorySize, smemA);
    cudaFuncSetAttribute(kernelBtc, cudaFuncAttributeMaxDynamicSharedMemorySize, smemB);

    kernelDM<<<dim3(NT, 7), dim3(32, 8)>>>(S);
    kernelA<<<dim3(5, NT), 160, smemA>>>(x, Att, Theta, out);
    kernelBtc<<<NT, 224, smemB>>>(Att, out);
}

// round 7
// speedup vs baseline: 2.1825x; 1.0787x over previous
#include <cuda_runtime.h>
#include <cstdint>

#define NN 8
#define TT 64
#define VV 200
#define FF 64
#define FOUT 64
#define NT 512
#define KC 16          // u per chunk in kernelBtc
#define NCH 13         // chunks: 12 full (16u) + 1 partial (8u)

typedef unsigned long long u64;
typedef unsigned int u32;

__device__ __forceinline__ u64 pack2(float x, float y) {
    u64 r; asm("mov.b64 %0, {%1,%2};" : "=l"(r) : "f"(x), "f"(y)); return r;
}
__device__ __forceinline__ float2 unpack2(u64 v) {
    float2 f; asm("mov.b64 {%0,%1}, %2;" : "=f"(f.x), "=f"(f.y) : "l"(v)); return f;
}
__device__ __forceinline__ u64 ffma2(u64 a, u64 b, u64 c) {
    u64 d; asm("fma.rn.f32x2 %0, %1, %2, %3;" : "=l"(d) : "l"(a), "l"(b), "l"(c)); return d;
}
__device__ __forceinline__ void cpa16(u32 dst, const void* src) {
    asm volatile("cp.async.cg.shared.global [%0], [%1], 16;" :: "r"(dst), "l"(src));
}
#define CP_COMMIT()   asm volatile("cp.async.commit_group;" ::: "memory")
#define CP_WAIT_ALL() asm volatile("cp.async.wait_group 0;" ::: "memory")

// TF32 mma: D += A*B, acc in-place. a,b are f32 bit patterns (HW uses tf32 bits).
__device__ __forceinline__ void mma8(float* d, const float* a, const float* bf) {
    asm volatile(
        "mma.sync.aligned.m16n8k8.row.col.f32.tf32.tf32.f32 "
        "{%0,%1,%2,%3},{%4,%5,%6,%7},{%8,%9},{%0,%1,%2,%3};"
        : "+f"(d[0]), "+f"(d[1]), "+f"(d[2]), "+f"(d[3])
        : "r"(__float_as_uint(a[0])), "r"(__float_as_uint(a[1])),
          "r"(__float_as_uint(a[2])), "r"(__float_as_uint(a[3])),
          "r"(__float_as_uint(bf[0])), "r"(__float_as_uint(bf[1])));
}

// scratch (static device globals; no runtime allocation)
__device__ __align__(16) float g_y1[(size_t)NT*VV*FOUT];
__device__ __align__(16) float g_y2[(size_t)NT*VV*FOUT];
__device__ __align__(16) float g_msym[(size_t)NT*VV*VV];
__device__ float g_d[(size_t)NT*VV];

// ---------------------------------------------------------------------------
// kernelDM: msym = min(S, S^T); d = row sums
// ---------------------------------------------------------------------------
__global__ void kernelDM(const float* __restrict__ S) {
    __shared__ float T[32][33];
    int nt = blockIdx.x;
    int u0 = blockIdx.y * 32;
    int uw = (VV - u0 < 32) ? (VV - u0) : 32;
    int tx = threadIdx.x, ty = threadIdx.y;
    const float* Snt = S + (size_t)nt * VV * VV;
    float* Mnt = g_msym + (size_t)nt * VV * VV;

    float dacc[4] = {0.f, 0.f, 0.f, 0.f};
    for (int v0 = 0; v0 < VV; v0 += 32) {
        int vw = (VV - v0 < 32) ? (VV - v0) : 32;
        __syncthreads();
        if (tx < uw)
            for (int vy = ty; vy < vw; vy += 8)
                T[vy][tx] = Snt[(size_t)(v0 + vy) * VV + u0 + tx];
        __syncthreads();
        if (tx < vw) {
#pragma unroll
            for (int k = 0; k < 4; ++k) {
                int uy = ty + k * 8;
                if (uy < uw) {
                    float a = Snt[(size_t)(u0 + uy) * VV + v0 + tx];
                    float m = fminf(a, T[tx][uy]);
                    Mnt[(size_t)(u0 + uy) * VV + v0 + tx] = m;
                    dacc[k] += m;
                }
            }
        }
    }
#pragma unroll
    for (int off = 16; off; off >>= 1)
#pragma unroll
        for (int k = 0; k < 4; ++k)
            dacc[k] += __shfl_down_sync(0xffffffffu, dacc[k], off);
    if (tx == 0)
#pragma unroll
        for (int k = 0; k < 4; ++k) {
            int uy = ty + k * 8;
            if (uy < uw) g_d[(size_t)nt * VV + u0 + uy] = dacc[k];
        }
}

// ---------------------------------------------------------------------------
// kernelA: y1/y2 = x@Theta{1,2} ([u][fo] layout); base = full diagonal term
//          (k=0,1,2 diag contributions, exact fp32) -> out
// ---------------------------------------------------------------------------
__global__ void __launch_bounds__(160, 3) kernelA(
        const float* __restrict__ x,
        const float* __restrict__ Att,
        const float* __restrict__ Theta,
        float* __restrict__ out_base) {
    extern __shared__ __align__(16) float sA[];
    float* Th = sA;                 // 3*64*64
    float* xs = sA + 3 * 64 * 64;   // 40*65 padded

    int u0  = blockIdx.x * 40;
    int nt  = blockIdx.y;
    int n   = nt / TT;
    int tid = threadIdx.x;

    {
        const float4* Tg = (const float4*)Theta;
        float4* Ts = (float4*)Th;
        for (int i = tid; i < 3 * 64 * 64 / 4; i += 160) Ts[i] = Tg[i];
    }
    {
        const float* xnt = x + (size_t)nt * VV * FF;
        for (int i = tid; i < 40 * 64; i += 160) {
            int r = i >> 6, c = i & 63;
            xs[r * 65 + c] = xnt[(size_t)(u0 + r) * FF + c];
        }
    }
    __syncthreads();

    int fo8 = tid & 7;
    int ug  = tid >> 3;
    const float* x0 = xs + (ug * 2) * 65;
    const float* x1 = x0 + 65;

    u64 acc[3][2][4];
#pragma unroll
    for (int k = 0; k < 3; ++k)
#pragma unroll
        for (int r = 0; r < 2; ++r)
#pragma unroll
            for (int j = 0; j < 4; ++j) acc[k][r][j] = 0ull;

    const ulonglong2* Tp = (const ulonglong2*)Th;
#pragma unroll 8
    for (int f = 0; f < 64; ++f) {
        u64 xv0 = pack2(x0[f], x0[f]);
        u64 xv1 = pack2(x1[f], x1[f]);
        int base = (f * 64 + fo8 * 8) >> 2;
#pragma unroll
        for (int k = 0; k < 3; ++k) {
            ulonglong2 ta = Tp[base + k * 1024];
            ulonglong2 tb = Tp[base + k * 1024 + 1];
            acc[k][0][0] = ffma2(xv0, ta.x, acc[k][0][0]);
            acc[k][0][1] = ffma2(xv0, ta.y, acc[k][0][1]);
            acc[k][0][2] = ffma2(xv0, tb.x, acc[k][0][2]);
            acc[k][0][3] = ffma2(xv0, tb.y, acc[k][0][3]);
            acc[k][1][0] = ffma2(xv1, ta.x, acc[k][1][0]);
            acc[k][1][1] = ffma2(xv1, ta.y, acc[k][1][1]);
            acc[k][1][2] = ffma2(xv1, tb.x, acc[k][1][2]);
            acc[k][1][3] = ffma2(xv1, tb.y, acc[k][1][3]);
        }
    }

#pragma unroll
    for (int r = 0; r < 2; ++r) {
        int u = u0 + ug * 2 + r;
        float att = Att[((size_t)n * VV + u) * VV + u];
        float duu = g_d[(size_t)nt * VV + u];
        float muu = g_msym[((size_t)nt * VV + u) * VV + u];
        float l = duu - 1.0f - muu;       // L_t diag
        float c1d = l * att;
        float c2d = (2.0f * l * l - 1.0f) * att;

        size_t ob = ((size_t)nt * VV + u) * FOUT + fo8 * 8;
        float ob8[8];
#pragma unroll
        for (int j = 0; j < 4; ++j) {
            float2 p0 = unpack2(acc[0][r][j]);
            float2 p1 = unpack2(acc[1][r][j]);
            float2 p2 = unpack2(acc[2][r][j]);
            ob8[2*j]   = att * p0.x + c1d * p1.x + c2d * p2.x;
            ob8[2*j+1] = att * p0.y + c1d * p1.y + c2d * p2.y;
        }
        *(float4*)(out_base + ob)     = make_float4(ob8[0], ob8[1], ob8[2], ob8[3]);
        *(float4*)(out_base + ob + 4) = make_float4(ob8[4], ob8[5], ob8[6], ob8[7]);
        *(ulonglong2*)(g_y1 + ob)     = make_ulonglong2(acc[1][r][0], acc[1][r][1]);
        *(ulonglong2*)(g_y1 + ob + 4) = make_ulonglong2(acc[1][r][2], acc[1][r][3]);
        *(ulonglong2*)(g_y2 + ob)     = make_ulonglong2(acc[2][r][0], acc[2][r][1]);
        *(ulonglong2*)(g_y2 + ob + 4) = make_ulonglong2(acc[2][r][2], acc[2][r][3]);
    }
}

// ---------------------------------------------------------------------------
// kernelBtc: TF32 mma.sync — out[v,fo] = relu(base + sum_{u!=v} c1*y1 + c2*y2)
// 1 CTA per nt, 224 threads (7 warps), warp w owns v in [32w, 32w+32).
// KC=16 chunks, double-buffered; smem 69.6 KB -> 3 CTAs/SM.
// smem (floats): m[2][16*200] | a[2][16*200] | y1[2][16*72] | y2[2][16*72]
// ---------------------------------------------------------------------------
#define OFF_M  0
#define OFF_A  6400
#define OFF_Y1 12800
#define OFF_Y2 15104
#define SMB_FLOATS 17408    // 69632 bytes

__global__ void __launch_bounds__(224) kernelBtc(const float* __restrict__ Att,
                                                 float* __restrict__ out) {
    extern __shared__ __align__(16) float sm[];
    int nt = blockIdx.x;
    int n  = nt / TT;
    int tid = threadIdx.x;
    int w = tid >> 5, lane = tid & 31;
    int g = lane >> 2, tg = lane & 3;
    int vbase = w * 32;

    const float* Mnt = g_msym + (size_t)nt * VV * VV;
    const float* Atn = Att + (size_t)n * VV * VV;
    const float* y1g = g_y1 + (size_t)nt * VV * FOUT;
    const float* y2g = g_y2 + (size_t)nt * VV * FOUT;

    float acc[2][8][4];
#pragma unroll
    for (int mt = 0; mt < 2; ++mt)
#pragma unroll
        for (int nn = 0; nn < 8; ++nn)
#pragma unroll
            for (int j = 0; j < 4; ++j) acc[mt][nn][j] = 0.f;

    auto stage = [&](int c, int b) {
        int u0 = c * KC;
        int uw = (c == NCH - 1) ? 8 : KC;
        for (int i = tid; i < uw * 50; i += 224) {
            int r = i / 50, s = i - r * 50;
            cpa16((u32)__cvta_generic_to_shared(sm + OFF_M + b * 3200 + r * 200 + s * 4),
                  Mnt + (size_t)(u0 + r) * VV + s * 4);
            cpa16((u32)__cvta_generic_to_shared(sm + OFF_A + b * 3200 + r * 200 + s * 4),
                  Atn + (size_t)(u0 + r) * VV + s * 4);
        }
        for (int i = tid; i < uw * 16; i += 224) {
            int r = i >> 4, s = i & 15;
            cpa16((u32)__cvta_generic_to_shared(sm + OFF_Y1 + b * 1152 + r * 72 + s * 4),
                  y1g + (size_t)(u0 + r) * FOUT + s * 4);
            cpa16((u32)__cvta_generic_to_shared(sm + OFF_Y2 + b * 1152 + r * 72 + s * 4),
                  y2g + (size_t)(u0 + r) * FOUT + s * 4);
        }
        CP_COMMIT();
    };

    stage(0, 0);

    for (int c = 0; c < NCH; ++c) {
        int b = c & 1;
        CP_WAIT_ALL();
        __syncthreads();             // chunk c data ready; all warps past mma(c-1)
        if (c + 1 < NCH) stage(c + 1, b ^ 1);

        int ks = (c == NCH - 1) ? 1 : 2;
        int u0 = c * KC;
        const float* mb  = sm + OFF_M  + b * 3200;
        const float* ab  = sm + OFF_A  + b * 3200;
        const float* y1b = sm + OFF_Y1 + b * 1152;
        const float* y2b = sm + OFF_Y2 + b * 1152;

        for (int k = 0; k < ks; ++k) {
            int cc0 = 8 * k + tg;        // local u col (A) / row (B)
            // ---- A fragments (coefficients inline, diag & OOB zeroed) ----
            float af1[2][4], af2[2][4];
#pragma unroll
            for (int mt = 0; mt < 2; ++mt) {
                int vA = vbase + 16 * mt + g;
                int vB = vA + 8;
                int ug0 = u0 + cc0, ug1 = ug0 + 4;
                int o0 = cc0 * 200, o1 = o0 + 800;   // (cc0+4)*200
                float m0 = mb[o0 + vA], a0 = ab[o0 + vA];
                float m1 = mb[o0 + vB], a1 = ab[o0 + vB];
                float m2 = mb[o1 + vA], a2 = ab[o1 + vA];
                float m3 = mb[o1 + vB], a3 = ab[o1 + vB];
                float am0 = m0 * a0, am1 = m1 * a1, am2 = m2 * a2, am3 = m3 * a3;
                bool k0 = (vA < VV) && (ug0 != vA);
                bool k1 = (vB < VV) && (ug0 != vB);
                bool k2 = (vA < VV) && (ug1 != vA);
                bool k3 = (vB < VV) && (ug1 != vB);
                af1[mt][0] = k0 ? -am0 : 0.f;  af2[mt][0] = k0 ? 2.f * m0 * am0 : 0.f;
                af1[mt][1] = k1 ? -am1 : 0.f;  af2[mt][1] = k1 ? 2.f * m1 * am1 : 0.f;
                af1[mt][2] = k2 ? -am2 : 0.f;  af2[mt][2] = k2 ? 2.f * m2 * am2 : 0.f;
                af1[mt][3] = k3 ? -am3 : 0.f;  af2[mt][3] = k3 ? 2.f * m3 * am3 : 0.f;
            }
            // ---- B fragments ----
            float bf1[8][2], bf2[8][2];
            int r0 = cc0 * 72 + g;
#pragma unroll
            for (int nn = 0; nn < 8; ++nn) {
                bf1[nn][0] = y1b[r0 + 8 * nn];
                bf1[nn][1] = y1b[r0 + 288 + 8 * nn];
                bf2[nn][0] = y2b[r0 + 8 * nn];
                bf2[nn][1] = y2b[r0 + 288 + 8 * nn];
            }
            // ---- 32 HMMA ----
#pragma unroll
            for (int mt = 0; mt < 2; ++mt)
#pragma unroll
                for (int nn = 0; nn < 8; ++nn) {
                    mma8(acc[mt][nn], af1[mt], bf1[nn]);
                    mma8(acc[mt][nn], af2[mt], bf2[nn]);
                }
        }
    }

    // ---- epilogue: base + D, relu, store ----
#pragma unroll
    for (int mt = 0; mt < 2; ++mt) {
        int v0 = vbase + 16 * mt + g;
        int v1 = v0 + 8;
#pragma unroll
        for (int nn = 0; nn < 8; ++nn) {
            int fo = nn * 8 + 2 * tg;
            if (v0 < VV) {
                float* p = out + ((size_t)nt * VV + v0) * FOUT + fo;
                float2 bse = *(const float2*)p;
                float2 o;
                o.x = fmaxf(bse.x + acc[mt][nn][0], 0.f);
                o.y = fmaxf(bse.y + acc[mt][nn][1], 0.f);
                *(float2*)p = o;
            }
            if (v1 < VV) {
                float* p = out + ((size_t)nt * VV + v1) * FOUT + fo;
                float2 bse = *(const float2*)p;
                float2 o;
                o.x = fmaxf(bse.x + acc[mt][nn][2], 0.f);
                o.y = fmaxf(bse.y + acc[mt][nn][3], 0.f);
                *(float2*)p = o;
            }
        }
    }
}

// ---------------------------------------------------------------------------
extern "C" void kernel_launch(void* const* d_in, const int* in_sizes, int n_in,
                              void* d_out, int out_size) {
    (void)in_sizes; (void)n_in; (void)out_size;
    const float* x     = (const float*)d_in[0];
    const float* Att   = (const float*)d_in[1];
    const float* S     = (const float*)d_in[2];
    const float* Theta = (const float*)d_in[3];
    float* out = (float*)d_out;

    const int smemA = (3 * 64 * 64 + 40 * 65) * 4;
    const int smemB = SMB_FLOATS * 4;     // 69632
    cudaFuncSetAttribute(kernelA,   cudaFuncAttributeMaxDynamicSharedMemorySize, smemA);
    cudaFuncSetAttribute(kernelBtc, cudaFuncAttributeMaxDynamicSharedMemorySize, smemB);

    kernelDM<<<dim3(NT, 7), dim3(32, 8)>>>(S);
    kernelA<<<dim3(5, NT), 160, smemA>>>(x, Att, Theta, out);
    kernelBtc<<<NT, 224, smemB>>>(Att, out);
}

// round 8
// speedup vs baseline: 2.1843x; 1.0008x over previous
#include <cuda_runtime.h>
#include <cstdint>

#define NN 8
#define TT 64
#define VV 200
#define FF 64
#define FOUT 64
#define NT 512
#define KC 16          // u per chunk in kernelBtc
#define NCH 13         // chunks: 12 full (16u) + 1 partial (8u)

typedef unsigned long long u64;
typedef unsigned int u32;

__device__ __forceinline__ u64 pack2(float x, float y) {
    u64 r; asm("mov.b64 %0, {%1,%2};" : "=l"(r) : "f"(x), "f"(y)); return r;
}
__device__ __forceinline__ float2 unpack2(u64 v) {
    float2 f; asm("mov.b64 {%0,%1}, %2;" : "=f"(f.x), "=f"(f.y) : "l"(v)); return f;
}
__device__ __forceinline__ u64 ffma2(u64 a, u64 b, u64 c) {
    u64 d; asm("fma.rn.f32x2 %0, %1, %2, %3;" : "=l"(d) : "l"(a), "l"(b), "l"(c)); return d;
}
__device__ __forceinline__ void cpa16(u32 dst, const void* src) {
    asm volatile("cp.async.cg.shared.global [%0], [%1], 16;" :: "r"(dst), "l"(src));
}
#define CP_COMMIT()   asm volatile("cp.async.commit_group;" ::: "memory")
#define CP_WAIT_ALL() asm volatile("cp.async.wait_group 0;" ::: "memory")

// pack two f32 -> bf16x2 (lo = first k element, hi = second)
__device__ __forceinline__ u32 cvt_bf2(float lo, float hi) {
    u32 r; asm("cvt.rn.bf16x2.f32 %0, %1, %2;" : "=r"(r) : "f"(hi), "f"(lo)); return r;
}

// BF16 mma m16n8k16: D += A*B (fp32 accum, in place)
__device__ __forceinline__ void mma16(float* d, const u32* a, const u32* b) {
    asm volatile(
        "mma.sync.aligned.m16n8k16.row.col.f32.bf16.bf16.f32 "
        "{%0,%1,%2,%3},{%4,%5,%6,%7},{%8,%9},{%0,%1,%2,%3};"
        : "+f"(d[0]), "+f"(d[1]), "+f"(d[2]), "+f"(d[3])
        : "r"(a[0]), "r"(a[1]), "r"(a[2]), "r"(a[3]),
          "r"(b[0]), "r"(b[1]));
}

// scratch (static device globals; no runtime allocation)
__device__ __align__(16) float g_y1[(size_t)NT*VV*FOUT];
__device__ __align__(16) float g_y2[(size_t)NT*VV*FOUT];
__device__ __align__(16) float g_msym[(size_t)NT*VV*VV];
__device__ float g_d[(size_t)NT*VV];

// ---------------------------------------------------------------------------
// kernelDM: msym = min(S, S^T); d = row sums
// ---------------------------------------------------------------------------
__global__ void kernelDM(const float* __restrict__ S) {
    __shared__ float T[32][33];
    int nt = blockIdx.x;
    int u0 = blockIdx.y * 32;
    int uw = (VV - u0 < 32) ? (VV - u0) : 32;
    int tx = threadIdx.x, ty = threadIdx.y;
    const float* Snt = S + (size_t)nt * VV * VV;
    float* Mnt = g_msym + (size_t)nt * VV * VV;

    float dacc[4] = {0.f, 0.f, 0.f, 0.f};
    for (int v0 = 0; v0 < VV; v0 += 32) {
        int vw = (VV - v0 < 32) ? (VV - v0) : 32;
        __syncthreads();
        if (tx < uw)
            for (int vy = ty; vy < vw; vy += 8)
                T[vy][tx] = Snt[(size_t)(v0 + vy) * VV + u0 + tx];
        __syncthreads();
        if (tx < vw) {
#pragma unroll
            for (int k = 0; k < 4; ++k) {
                int uy = ty + k * 8;
                if (uy < uw) {
                    float a = Snt[(size_t)(u0 + uy) * VV + v0 + tx];
                    float m = fminf(a, T[tx][uy]);
                    Mnt[(size_t)(u0 + uy) * VV + v0 + tx] = m;
                    dacc[k] += m;
                }
            }
        }
    }
#pragma unroll
    for (int off = 16; off; off >>= 1)
#pragma unroll
        for (int k = 0; k < 4; ++k)
            dacc[k] += __shfl_down_sync(0xffffffffu, dacc[k], off);
    if (tx == 0)
#pragma unroll
        for (int k = 0; k < 4; ++k) {
            int uy = ty + k * 8;
            if (uy < uw) g_d[(size_t)nt * VV + u0 + uy] = dacc[k];
        }
}

// ---------------------------------------------------------------------------
// kernelA: y1/y2 = x@Theta{1,2} ([u][fo] fp32); base = full diagonal term
// ---------------------------------------------------------------------------
__global__ void __launch_bounds__(160, 3) kernelA(
        const float* __restrict__ x,
        const float* __restrict__ Att,
        const float* __restrict__ Theta,
        float* __restrict__ out_base) {
    extern __shared__ __align__(16) float sA[];
    float* Th = sA;                 // 3*64*64
    float* xs = sA + 3 * 64 * 64;   // 40*65 padded

    int u0  = blockIdx.x * 40;
    int nt  = blockIdx.y;
    int n   = nt / TT;
    int tid = threadIdx.x;

    {
        const float4* Tg = (const float4*)Theta;
        float4* Ts = (float4*)Th;
        for (int i = tid; i < 3 * 64 * 64 / 4; i += 160) Ts[i] = Tg[i];
    }
    {
        const float* xnt = x + (size_t)nt * VV * FF;
        for (int i = tid; i < 40 * 64; i += 160) {
            int r = i >> 6, c = i & 63;
            xs[r * 65 + c] = xnt[(size_t)(u0 + r) * FF + c];
        }
    }
    __syncthreads();

    int fo8 = tid & 7;
    int ug  = tid >> 3;
    const float* x0 = xs + (ug * 2) * 65;
    const float* x1 = x0 + 65;

    u64 acc[3][2][4];
#pragma unroll
    for (int k = 0; k < 3; ++k)
#pragma unroll
        for (int r = 0; r < 2; ++r)
#pragma unroll
            for (int j = 0; j < 4; ++j) acc[k][r][j] = 0ull;

    const ulonglong2* Tp = (const ulonglong2*)Th;
#pragma unroll 8
    for (int f = 0; f < 64; ++f) {
        u64 xv0 = pack2(x0[f], x0[f]);
        u64 xv1 = pack2(x1[f], x1[f]);
        int base = (f * 64 + fo8 * 8) >> 2;
#pragma unroll
        for (int k = 0; k < 3; ++k) {
            ulonglong2 ta = Tp[base + k * 1024];
            ulonglong2 tb = Tp[base + k * 1024 + 1];
            acc[k][0][0] = ffma2(xv0, ta.x, acc[k][0][0]);
            acc[k][0][1] = ffma2(xv0, ta.y, acc[k][0][1]);
            acc[k][0][2] = ffma2(xv0, tb.x, acc[k][0][2]);
            acc[k][0][3] = ffma2(xv0, tb.y, acc[k][0][3]);
            acc[k][1][0] = ffma2(xv1, ta.x, acc[k][1][0]);
            acc[k][1][1] = ffma2(xv1, ta.y, acc[k][1][1]);
            acc[k][1][2] = ffma2(xv1, tb.x, acc[k][1][2]);
            acc[k][1][3] = ffma2(xv1, tb.y, acc[k][1][3]);
        }
    }

#pragma unroll
    for (int r = 0; r < 2; ++r) {
        int u = u0 + ug * 2 + r;
        float att = Att[((size_t)n * VV + u) * VV + u];
        float duu = g_d[(size_t)nt * VV + u];
        float muu = g_msym[((size_t)nt * VV + u) * VV + u];
        float l = duu - 1.0f - muu;       // L_t diag
        float c1d = l * att;
        float c2d = (2.0f * l * l - 1.0f) * att;

        size_t ob = ((size_t)nt * VV + u) * FOUT + fo8 * 8;
        float ob8[8];
#pragma unroll
        for (int j = 0; j < 4; ++j) {
            float2 p0 = unpack2(acc[0][r][j]);
            float2 p1 = unpack2(acc[1][r][j]);
            float2 p2 = unpack2(acc[2][r][j]);
            ob8[2*j]   = att * p0.x + c1d * p1.x + c2d * p2.x;
            ob8[2*j+1] = att * p0.y + c1d * p1.y + c2d * p2.y;
        }
        *(float4*)(out_base + ob)     = make_float4(ob8[0], ob8[1], ob8[2], ob8[3]);
        *(float4*)(out_base + ob + 4) = make_float4(ob8[4], ob8[5], ob8[6], ob8[7]);
        *(ulonglong2*)(g_y1 + ob)     = make_ulonglong2(acc[1][r][0], acc[1][r][1]);
        *(ulonglong2*)(g_y1 + ob + 4) = make_ulonglong2(acc[1][r][2], acc[1][r][3]);
        *(ulonglong2*)(g_y2 + ob)     = make_ulonglong2(acc[2][r][0], acc[2][r][1]);
        *(ulonglong2*)(g_y2 + ob + 4) = make_ulonglong2(acc[2][r][2], acc[2][r][3]);
    }
}

// ---------------------------------------------------------------------------
// kernelBtc (BF16 m16n8k16): out[v,fo] = relu(base + sum_{u!=v} c1*y1 + c2*y2)
// 1 CTA per nt, 224 threads (7 warps), warp w owns v in [32w, 32w+32).
// KC=16 chunks, double-buffered. m/a stride 228 fl, y stride 68 fl
// (bank-conflict-free for the fragment lane patterns; 16B-aligned rows).
// ---------------------------------------------------------------------------
#define SMA 228                 // m/a row stride (floats)
#define SMY 68                  // y row stride (floats)
#define BUF_MA (KC * SMA)       // 3648
#define BUF_Y  (KC * SMY)       // 1088
#define OFF_M  0
#define OFF_A  (2 * BUF_MA)             // 7296
#define OFF_Y1 (4 * BUF_MA)             // 14592
#define OFF_Y2 (4 * BUF_MA + 2 * BUF_Y) // 16768
#define SMB_FLOATS (4 * BUF_MA + 4 * BUF_Y)  // 18944 fl = 75776 B

__global__ void __launch_bounds__(224) kernelBtc(const float* __restrict__ Att,
                                                 float* __restrict__ out) {
    extern __shared__ __align__(16) float sm[];
    int nt = blockIdx.x;
    int n  = nt / TT;
    int tid = threadIdx.x;
    int w = tid >> 5, lane = tid & 31;
    int g = lane >> 2, tg = lane & 3;
    int vbase = w * 32;

    const float* Mnt = g_msym + (size_t)nt * VV * VV;
    const float* Atn = Att + (size_t)n * VV * VV;
    const float* y1g = g_y1 + (size_t)nt * VV * FOUT;
    const float* y2g = g_y2 + (size_t)nt * VV * FOUT;

    float acc[2][8][4];
#pragma unroll
    for (int mt = 0; mt < 2; ++mt)
#pragma unroll
        for (int nn = 0; nn < 8; ++nn)
#pragma unroll
            for (int j = 0; j < 4; ++j) acc[mt][nn][j] = 0.f;

    auto stage = [&](int c, int b) {
        int u0 = c * KC;
        int uw = (c == NCH - 1) ? 8 : KC;
        for (int i = tid; i < uw * 50; i += 224) {
            int r = i / 50, s = i - r * 50;
            cpa16((u32)__cvta_generic_to_shared(sm + OFF_M + b * BUF_MA + r * SMA + s * 4),
                  Mnt + (size_t)(u0 + r) * VV + s * 4);
            cpa16((u32)__cvta_generic_to_shared(sm + OFF_A + b * BUF_MA + r * SMA + s * 4),
                  Atn + (size_t)(u0 + r) * VV + s * 4);
        }
        for (int i = tid; i < uw * 16; i += 224) {
            int r = i >> 4, s = i & 15;
            cpa16((u32)__cvta_generic_to_shared(sm + OFF_Y1 + b * BUF_Y + r * SMY + s * 4),
                  y1g + (size_t)(u0 + r) * FOUT + s * 4);
            cpa16((u32)__cvta_generic_to_shared(sm + OFF_Y2 + b * BUF_Y + r * SMY + s * 4),
                  y2g + (size_t)(u0 + r) * FOUT + s * 4);
        }
        CP_COMMIT();
    };

    stage(0, 0);

    // local u rows used by this lane's fragments (k16: pairs along u)
    int uA = 2 * tg, uC = 2 * tg + 8;

    for (int c = 0; c < NCH; ++c) {
        int b = c & 1;
        CP_WAIT_ALL();
        __syncthreads();             // chunk c ready; all warps past mma(c-1)
        if (c + 1 < NCH) stage(c + 1, b ^ 1);

        int u0 = c * KC;
        const float* mb  = sm + OFF_M  + b * BUF_MA;
        const float* ab  = sm + OFF_A  + b * BUF_MA;
        const float* y1b = sm + OFF_Y1 + b * BUF_Y;
        const float* y2b = sm + OFF_Y2 + b * BUF_Y;

        // ---- B fragments: pack (u even, u odd) pairs into bf16x2 ----
        u32 b1r[8][2], b2r[8][2];
#pragma unroll
        for (int nn = 0; nn < 8; ++nn) {
            int fo = 8 * nn + g;
            b1r[nn][0] = cvt_bf2(y1b[uA * SMY + fo], y1b[(uA + 1) * SMY + fo]);
            b1r[nn][1] = cvt_bf2(y1b[uC * SMY + fo], y1b[(uC + 1) * SMY + fo]);
            b2r[nn][0] = cvt_bf2(y2b[uA * SMY + fo], y2b[(uA + 1) * SMY + fo]);
            b2r[nn][1] = cvt_bf2(y2b[uC * SMY + fo], y2b[(uC + 1) * SMY + fo]);
        }

        // ---- A fragments: coefficients inline (diag & OOB -> 0), bf16x2 ----
        u32 af1[2][4], af2[2][4];
#pragma unroll
        for (int mt = 0; mt < 2; ++mt) {
            int vA = vbase + 16 * mt + g;
            int vB = vA + 8;
            float c1v[2][4], c2v[2][4];   // [row(vA/vB)][u-slot: uA,uA+1,uC,uC+1]
#pragma unroll
            for (int s = 0; s < 4; ++s) {
                int ul = (s < 2) ? (uA + s) : (uC + s - 2);
                int ugl = u0 + ul;
                float mA = mb[ul * SMA + vA], aA = ab[ul * SMA + vA];
                float mB = mb[ul * SMA + vB], aB = ab[ul * SMA + vB];
                float p1A = -mA * aA, p2A = -2.f * mA * p1A;
                float p1B = -mB * aB, p2B = -2.f * mB * p1B;
                bool okA = (ugl < VV) && (vA < VV) && (ugl != vA);
                bool okB = (ugl < VV) && (vB < VV) && (ugl != vB);
                c1v[0][s] = okA ? p1A : 0.f;  c2v[0][s] = okA ? p2A : 0.f;
                c1v[1][s] = okB ? p1B : 0.f;  c2v[1][s] = okB ? p2B : 0.f;
            }
            af1[mt][0] = cvt_bf2(c1v[0][0], c1v[0][1]);
            af1[mt][1] = cvt_bf2(c1v[1][0], c1v[1][1]);
            af1[mt][2] = cvt_bf2(c1v[0][2], c1v[0][3]);
            af1[mt][3] = cvt_bf2(c1v[1][2], c1v[1][3]);
            af2[mt][0] = cvt_bf2(c2v[0][0], c2v[0][1]);
            af2[mt][1] = cvt_bf2(c2v[1][0], c2v[1][1]);
            af2[mt][2] = cvt_bf2(c2v[0][2], c2v[0][3]);
            af2[mt][3] = cvt_bf2(c2v[1][2], c2v[1][3]);
        }

        // ---- 32 HMMA (bf16 k16) ----
#pragma unroll
        for (int mt = 0; mt < 2; ++mt)
#pragma unroll
            for (int nn = 0; nn < 8; ++nn) {
                mma16(acc[mt][nn], af1[mt], b1r[nn]);
                mma16(acc[mt][nn], af2[mt], b2r[nn]);
            }
    }

    // ---- epilogue: base + D, relu, store ----
#pragma unroll
    for (int mt = 0; mt < 2; ++mt) {
        int v0 = vbase + 16 * mt + g;
        int v1 = v0 + 8;
#pragma unroll
        for (int nn = 0; nn < 8; ++nn) {
            int fo = nn * 8 + 2 * tg;
            if (v0 < VV) {
                float* p = out + ((size_t)nt * VV + v0) * FOUT + fo;
                float2 bse = *(const float2*)p;
                float2 o;
                o.x = fmaxf(bse.x + acc[mt][nn][0], 0.f);
                o.y = fmaxf(bse.y + acc[mt][nn][1], 0.f);
                *(float2*)p = o;
            }
            if (v1 < VV) {
                float* p = out + ((size_t)nt * VV + v1) * FOUT + fo;
                float2 bse = *(const float2*)p;
                float2 o;
                o.x = fmaxf(bse.x + acc[mt][nn][2], 0.f);
                o.y = fmaxf(bse.y + acc[mt][nn][3], 0.f);
                *(float2*)p = o;
            }
        }
    }
}

// ---------------------------------------------------------------------------
extern "C" void kernel_launch(void* const* d_in, const int* in_sizes, int n_in,
                              void* d_out, int out_size) {
    (void)in_sizes; (void)n_in; (void)out_size;
    const float* x     = (const float*)d_in[0];
    const float* Att   = (const float*)d_in[1];
    const float* S     = (const float*)d_in[2];
    const float* Theta = (const float*)d_in[3];
    float* out = (float*)d_out;

    const int smemA = (3 * 64 * 64 + 40 * 65) * 4;
    const int smemB = SMB_FLOATS * 4;     // 75776
    cudaFuncSetAttribute(kernelA,   cudaFuncAttributeMaxDynamicSharedMemorySize, smemA);
    cudaFuncSetAttribute(kernelBtc, cudaFuncAttributeMaxDynamicSharedMemorySize, smemB);

    kernelDM<<<dim3(NT, 7), dim3(32, 8)>>>(S);
    kernelA<<<dim3(5, NT), 160, smemA>>>(x, Att, Theta, out);
    kernelBtc<<<NT, 224, smemB>>>(Att, out);
}